// round 2
// baseline (speedup 1.0000x reference)
#include <cuda_runtime.h>
#include <cuda_bf16.h>

// Problem constants
#define N 4096
#define D 512
#define NC 100          // real classes
#define NCP 128         // padded classes
#define ROWS_B 32       // rows per GEMM block
#define KT 32           // k-tile

// Scratch (device globals; no allocation in kernel_launch)
__device__ __align__(16) float g_txt_n[N * D];   // normalized text features
__device__ float g_d[N];                          // per-row <img_n, txt_n>
__device__ float g_G[NC * D];                     // class sums of img_n, layout [c][d]
__device__ int   g_cnt[NCP];                      // class counts
__device__ double g_neg[1];                       // neg_similarity accumulator

// ---------------------------------------------------------------------------
// Kernel 0: zero scratch accumulators (must run every replay)
// ---------------------------------------------------------------------------
__global__ void zero_kernel() {
    int idx = blockIdx.x * blockDim.x + threadIdx.x;
    if (idx < NC * D) g_G[idx] = 0.0f;
    if (idx < NCP)    g_cnt[idx] = 0;
    if (idx == 0)     g_neg[0] = 0.0;
}

// ---------------------------------------------------------------------------
// Kernel 1: per-row normalize, store txt_n, d_i, scatter img_n into G
// grid = N blocks, 128 threads (each thread owns 4 consecutive dims, float4)
// ---------------------------------------------------------------------------
__global__ void __launch_bounds__(128) rownorm_kernel(
    const float* __restrict__ img,
    const float* __restrict__ txt,
    const int* __restrict__ labels)
{
    const int i   = blockIdx.x;
    const int tid = threadIdx.x;
    const int lane = tid & 31;
    const int warp = tid >> 5;

    const float4 a = reinterpret_cast<const float4*>(img + (size_t)i * D)[tid];
    const float4 b = reinterpret_cast<const float4*>(txt + (size_t)i * D)[tid];

    float sii = a.x*a.x + a.y*a.y + a.z*a.z + a.w*a.w;
    float stt = b.x*b.x + b.y*b.y + b.z*b.z + b.w*b.w;
    float sit = a.x*b.x + a.y*b.y + a.z*b.z + a.w*b.w;

    // warp reduce 3 sums
    #pragma unroll
    for (int off = 16; off > 0; off >>= 1) {
        sii += __shfl_xor_sync(0xffffffffu, sii, off);
        stt += __shfl_xor_sync(0xffffffffu, stt, off);
        sit += __shfl_xor_sync(0xffffffffu, sit, off);
    }
    __shared__ float red[3][4];
    if (lane == 0) { red[0][warp] = sii; red[1][warp] = stt; red[2][warp] = sit; }
    __syncthreads();
    // broadcast totals via all threads summing 4 warp partials (cheap)
    sii = red[0][0] + red[0][1] + red[0][2] + red[0][3];
    stt = red[1][0] + red[1][1] + red[1][2] + red[1][3];
    sit = red[2][0] + red[2][1] + red[2][2] + red[2][3];

    const float rimg = rsqrtf(sii);
    const float rtxt = rsqrtf(stt);
    // labels are int32 on device (JAX x64-disabled demotes int64).
    // Clamp for guaranteed memory safety.
    int c = labels[i];
    c = min(max(c, 0), NC - 1);

    // store normalized text row
    float4 tn;
    tn.x = b.x * rtxt; tn.y = b.y * rtxt; tn.z = b.z * rtxt; tn.w = b.w * rtxt;
    reinterpret_cast<float4*>(g_txt_n + (size_t)i * D)[tid] = tn;

    // scatter normalized image row into class sum G[c][:] (coalesced REDG)
    float* gc = g_G + (size_t)c * D + tid * 4;
    atomicAdd(gc + 0, a.x * rimg);
    atomicAdd(gc + 1, a.y * rimg);
    atomicAdd(gc + 2, a.z * rimg);
    atomicAdd(gc + 3, a.w * rimg);

    if (tid == 0) {
        g_d[i] = sit * rimg * rtxt;
        atomicAdd(&g_cnt[c], 1);
    }
}

// ---------------------------------------------------------------------------
// Kernel 2: C = txt_n @ G^T  (rows x classes), fused with neg reduction.
// grid = N/ROWS_B = 128 blocks, 256 threads.
// Thread tile: 4 rows (warp owns 4 rows) x 4 classes (lane + 32j).
// ---------------------------------------------------------------------------
__global__ void __launch_bounds__(256) gemm_neg_kernel() {
    __shared__ float As[ROWS_B][KT + 1];     // [row][k]
    __shared__ float Bs[KT][NCP + 4];        // [k][class], pad to kill conflicts
    __shared__ float ns[NCP];

    const int tid  = threadIdx.x;
    const int lane = tid & 31;
    const int warp = tid >> 5;                // warp w owns rows 4w..4w+3
    const int row0 = blockIdx.x * ROWS_B;

    if (tid < NCP) ns[tid] = (tid < NC) ? (float)g_cnt[tid] : 0.0f;

    float acc[4][4] = {};

    for (int k0 = 0; k0 < D; k0 += KT) {
        // A tile: 32x32, 4 elems/thread, coalesced in k
        #pragma unroll
        for (int e = 0; e < 4; e++) {
            int idx = tid + e * 256;
            int r = idx >> 5, k = idx & 31;
            As[r][k] = g_txt_n[(size_t)(row0 + r) * D + k0 + k];
        }
        // B tile: 128x32 from G[c][k], stored transposed Bs[k][c]
        #pragma unroll
        for (int e = 0; e < 16; e++) {
            int idx = tid + e * 256;
            int c = idx >> 5, k = idx & 31;
            Bs[k][c] = (c < NC) ? g_G[(size_t)c * D + k0 + k] : 0.0f;
        }
        __syncthreads();

        #pragma unroll
        for (int kk = 0; kk < KT; kk++) {
            float a[4], b[4];
            #pragma unroll
            for (int ii = 0; ii < 4; ii++) a[ii] = As[warp * 4 + ii][kk];
            #pragma unroll
            for (int jj = 0; jj < 4; jj++) b[jj] = Bs[kk][lane + 32 * jj];
            #pragma unroll
            for (int ii = 0; ii < 4; ii++)
                #pragma unroll
                for (int jj = 0; jj < 4; jj++)
                    acc[ii][jj] = fmaf(a[ii], b[jj], acc[ii][jj]);
        }
        __syncthreads();
    }

    // Epilogue: per row i: S = sum_c C[i,c]; neg += sum_c n_c * exp(S - C[i,c])
    double warp_neg = 0.0;
    #pragma unroll
    for (int ii = 0; ii < 4; ii++) {
        float s = acc[ii][0] + acc[ii][1] + acc[ii][2] + acc[ii][3];
        #pragma unroll
        for (int off = 16; off > 0; off >>= 1)
            s += __shfl_xor_sync(0xffffffffu, s, off);   // S_i (allreduce)
        float p = 0.0f;
        #pragma unroll
        for (int jj = 0; jj < 4; jj++)
            p += ns[lane + 32 * jj] * expf(s - acc[ii][jj]);
        #pragma unroll
        for (int off = 16; off > 0; off >>= 1)
            p += __shfl_xor_sync(0xffffffffu, p, off);
        warp_neg += (double)p;
    }
    if (lane == 0) atomicAdd(&g_neg[0], warp_neg);
}

// ---------------------------------------------------------------------------
// Kernel 3: loss = sum_i [ log(exp(d_i) + neg) - d_i ]
// ---------------------------------------------------------------------------
__global__ void __launch_bounds__(256) finish_kernel(float* __restrict__ out) {
    __shared__ double red[8];
    const int tid = threadIdx.x;
    const float neg = (float)g_neg[0];

    double sum = 0.0;
    for (int i = tid; i < N; i += 256) {
        float d = g_d[i];
        sum += (double)(logf(expf(d) + neg) - d);
    }
    #pragma unroll
    for (int off = 16; off > 0; off >>= 1)
        sum += __shfl_xor_sync(0xffffffffu, sum, off);
    if ((tid & 31) == 0) red[tid >> 5] = sum;
    __syncthreads();
    if (tid == 0) {
        double t = 0.0;
        #pragma unroll
        for (int w = 0; w < 8; w++) t += red[w];
        out[0] = (float)t;
    }
}

// ---------------------------------------------------------------------------
extern "C" void kernel_launch(void* const* d_in, const int* in_sizes, int n_in,
                              void* d_out, int out_size) {
    const float* img    = (const float*)d_in[0];
    const float* txt    = (const float*)d_in[1];
    const int*   labels = (const int*)d_in[2];
    float* out = (float*)d_out;

    zero_kernel<<<(NC * D + 255) / 256, 256>>>();
    rownorm_kernel<<<N, 128>>>(img, txt, labels);
    gemm_neg_kernel<<<N / ROWS_B, 256>>>();
    finish_kernel<<<1, 256>>>(out);
}

// round 3
// speedup vs baseline: 1.3339x; 1.3339x over previous
#include <cuda_runtime.h>
#include <cuda_bf16.h>

// Problem constants
#define N 4096
#define D 512
#define NC 100          // real classes
#define NCP 128         // padded classes
#define ROWS_B 32       // rows per GEMM block
#define KT 32           // k-tile

// Packed fp32x2 FMA (Blackwell): d = a*b + d elementwise on 2 floats
#define FMA2(d, a, b) \
    asm("fma.rn.f32x2 %0, %1, %2, %3;" : "=l"(d) : "l"(a), "l"(b), "l"(d))
#define SPLAT2(d, f) \
    asm("mov.b64 %0, {%1, %1};" : "=l"(d) : "f"(f))

// Scratch (device globals; no allocation in kernel_launch)
__device__ __align__(16) float g_txt_n[N * D];   // normalized text features
__device__ float g_d[N];                          // per-row <img_n, txt_n>
__device__ __align__(16) float g_G[NC * D];       // class sums of img_n, [c][d]
__device__ int    g_cnt[NCP];                     // class counts
__device__ double g_neg[1];                       // neg_similarity accumulator
__device__ double g_loss[1];                      // loss accumulator
__device__ unsigned int g_ticket[1];              // finish-kernel ticket

// ---------------------------------------------------------------------------
// Kernel 0: zero scratch accumulators (must run every replay)
// ---------------------------------------------------------------------------
__global__ void zero_kernel() {
    int idx = blockIdx.x * blockDim.x + threadIdx.x;
    if (idx < NC * D) g_G[idx] = 0.0f;
    if (idx < NCP)    g_cnt[idx] = 0;
    if (idx == 0) { g_neg[0] = 0.0; g_loss[0] = 0.0; g_ticket[0] = 0u; }
}

// ---------------------------------------------------------------------------
// Kernel 1: per-row normalize, store txt_n, d_i, scatter img_n into G
// grid = N blocks, 128 threads (each thread owns 4 consecutive dims, float4)
// ---------------------------------------------------------------------------
__global__ void __launch_bounds__(128) rownorm_kernel(
    const float* __restrict__ img,
    const float* __restrict__ txt,
    const int* __restrict__ labels)
{
    const int i    = blockIdx.x;
    const int tid  = threadIdx.x;
    const int lane = tid & 31;
    const int warp = tid >> 5;

    const float4 a = reinterpret_cast<const float4*>(img + (size_t)i * D)[tid];
    const float4 b = reinterpret_cast<const float4*>(txt + (size_t)i * D)[tid];

    float sii = a.x*a.x + a.y*a.y + a.z*a.z + a.w*a.w;
    float stt = b.x*b.x + b.y*b.y + b.z*b.z + b.w*b.w;
    float sit = a.x*b.x + a.y*b.y + a.z*b.z + a.w*b.w;

    #pragma unroll
    for (int off = 16; off > 0; off >>= 1) {
        sii += __shfl_xor_sync(0xffffffffu, sii, off);
        stt += __shfl_xor_sync(0xffffffffu, stt, off);
        sit += __shfl_xor_sync(0xffffffffu, sit, off);
    }
    __shared__ float red[3][4];
    if (lane == 0) { red[0][warp] = sii; red[1][warp] = stt; red[2][warp] = sit; }
    __syncthreads();
    sii = red[0][0] + red[0][1] + red[0][2] + red[0][3];
    stt = red[1][0] + red[1][1] + red[1][2] + red[1][3];
    sit = red[2][0] + red[2][1] + red[2][2] + red[2][3];

    const float rimg = rsqrtf(sii);
    const float rtxt = rsqrtf(stt);
    int c = labels[i];
    c = min(max(c, 0), NC - 1);

    float4 tn;
    tn.x = b.x * rtxt; tn.y = b.y * rtxt; tn.z = b.z * rtxt; tn.w = b.w * rtxt;
    reinterpret_cast<float4*>(g_txt_n + (size_t)i * D)[tid] = tn;

    float* gc = g_G + (size_t)c * D + tid * 4;
    atomicAdd(gc + 0, a.x * rimg);
    atomicAdd(gc + 1, a.y * rimg);
    atomicAdd(gc + 2, a.z * rimg);
    atomicAdd(gc + 3, a.w * rimg);

    if (tid == 0) {
        g_d[i] = sit * rimg * rtxt;
        atomicAdd(&g_cnt[c], 1);
    }
}

// ---------------------------------------------------------------------------
// Kernel 2: C = txt_n @ G^T fused with neg reduction, packed f32x2 FMA.
// grid = N/ROWS_B = 128 blocks, 256 threads.
// Warp w owns rows 4w..4w+3; lane L owns class pairs (2L,2L+1),(2L+64,2L+65).
// ---------------------------------------------------------------------------
__global__ void __launch_bounds__(256) gemm_neg_kernel() {
    __shared__ float As[ROWS_B][KT + 1];   // [row][k], broadcast reads
    __shared__ float Bs[KT][NCP + 2];      // [k][class], stride 130 (8B-aligned rows)

    const int tid  = threadIdx.x;
    const int lane = tid & 31;
    const int warp = tid >> 5;
    const int row0 = blockIdx.x * ROWS_B;

    // class counts for this lane's 4 classes (padded classes have count 0)
    const float n0 = (float)g_cnt[2*lane];
    const float n1 = (float)g_cnt[2*lane + 1];
    const float n2 = (float)g_cnt[2*lane + 64];
    const float n3 = (float)g_cnt[2*lane + 65];

    // accumulators: 4 rows x 2 packed class-pairs
    unsigned long long accp[4][2] = {};

    // load-tile addressing (constant per thread)
    const int ar  = tid >> 3;            // A row 0..31
    const int ak4 = (tid & 7) * 4;       // A k offset 0..28

    float4 aReg;
    float4 bReg[4];
    const float4 zero4 = make_float4(0.f, 0.f, 0.f, 0.f);

    // prefetch tile 0
    aReg = *reinterpret_cast<const float4*>(&g_txt_n[(size_t)(row0 + ar) * D + ak4]);
    #pragma unroll
    for (int e = 0; e < 4; e++) {
        int idx = tid + e * 256;
        int c = idx >> 3, k4 = (idx & 7) * 4;
        bReg[e] = (c < NC)
            ? *reinterpret_cast<const float4*>(&g_G[(size_t)c * D + k4])
            : zero4;
    }

    for (int t = 0; t < D / KT; t++) {
        // commit prefetched tile to smem
        As[ar][ak4 + 0] = aReg.x;
        As[ar][ak4 + 1] = aReg.y;
        As[ar][ak4 + 2] = aReg.z;
        As[ar][ak4 + 3] = aReg.w;
        #pragma unroll
        for (int e = 0; e < 4; e++) {
            int idx = tid + e * 256;
            int c = idx >> 3, k4 = (idx & 7) * 4;
            Bs[k4 + 0][c] = bReg[e].x;
            Bs[k4 + 1][c] = bReg[e].y;
            Bs[k4 + 2][c] = bReg[e].z;
            Bs[k4 + 3][c] = bReg[e].w;
        }
        __syncthreads();

        // prefetch next tile (overlaps compute)
        if (t < D / KT - 1) {
            int k0 = (t + 1) * KT;
            aReg = *reinterpret_cast<const float4*>(&g_txt_n[(size_t)(row0 + ar) * D + k0 + ak4]);
            #pragma unroll
            for (int e = 0; e < 4; e++) {
                int idx = tid + e * 256;
                int c = idx >> 3, k4 = (idx & 7) * 4;
                bReg[e] = (c < NC)
                    ? *reinterpret_cast<const float4*>(&g_G[(size_t)c * D + k0 + k4])
                    : zero4;
            }
        }

        // compute: packed f32x2 FMAs
        #pragma unroll
        for (int kk = 0; kk < KT; kk++) {
            const unsigned long long b0 =
                *reinterpret_cast<const unsigned long long*>(&Bs[kk][2 * lane]);
            const unsigned long long b1 =
                *reinterpret_cast<const unsigned long long*>(&Bs[kk][2 * lane + 64]);
            #pragma unroll
            for (int ii = 0; ii < 4; ii++) {
                float av = As[warp * 4 + ii][kk];
                unsigned long long ap;
                SPLAT2(ap, av);
                FMA2(accp[ii][0], ap, b0);
                FMA2(accp[ii][1], ap, b1);
            }
        }
        __syncthreads();
    }

    // Epilogue: per row i: S = sum_c C[i,c]; neg += sum_c n_c * exp(S - C[i,c])
    double warp_neg = 0.0;
    #pragma unroll
    for (int ii = 0; ii < 4; ii++) {
        float c00, c01, c10, c11;
        asm("mov.b64 {%0, %1}, %2;" : "=f"(c00), "=f"(c01) : "l"(accp[ii][0]));
        asm("mov.b64 {%0, %1}, %2;" : "=f"(c10), "=f"(c11) : "l"(accp[ii][1]));
        float s = c00 + c01 + c10 + c11;
        #pragma unroll
        for (int off = 16; off > 0; off >>= 1)
            s += __shfl_xor_sync(0xffffffffu, s, off);   // S_i allreduce
        float p = n0 * expf(s - c00) + n1 * expf(s - c01)
                + n2 * expf(s - c10) + n3 * expf(s - c11);
        #pragma unroll
        for (int off = 16; off > 0; off >>= 1)
            p += __shfl_xor_sync(0xffffffffu, p, off);
        warp_neg += (double)p;
    }
    if (lane == 0) atomicAdd(&g_neg[0], warp_neg);
}

// ---------------------------------------------------------------------------
// Kernel 3: loss = sum_i [ log(exp(d_i) + neg) - d_i ]
// 16 blocks x 256 threads, 1 element/thread; ticketed final write.
// ---------------------------------------------------------------------------
__global__ void __launch_bounds__(256) finish_kernel(float* __restrict__ out) {
    __shared__ double red[8];
    const int tid = threadIdx.x;
    const int i   = blockIdx.x * 256 + tid;
    const float neg = (float)g_neg[0];

    const float d = g_d[i];
    double sum = (double)(logf(expf(d) + neg) - d);

    #pragma unroll
    for (int off = 16; off > 0; off >>= 1)
        sum += __shfl_xor_sync(0xffffffffu, sum, off);
    if ((tid & 31) == 0) red[tid >> 5] = sum;
    __syncthreads();

    if (tid == 0) {
        double bsum = 0.0;
        #pragma unroll
        for (int w = 0; w < 8; w++) bsum += red[w];
        atomicAdd(&g_loss[0], bsum);
        __threadfence();
        unsigned int t = atomicAdd(&g_ticket[0], 1u);
        if (t == gridDim.x - 1) {
            double total = atomicAdd(&g_loss[0], 0.0);  // coherent read
            out[0] = (float)total;
        }
    }
}

// ---------------------------------------------------------------------------
extern "C" void kernel_launch(void* const* d_in, const int* in_sizes, int n_in,
                              void* d_out, int out_size) {
    const float* img    = (const float*)d_in[0];
    const float* txt    = (const float*)d_in[1];
    const int*   labels = (const int*)d_in[2];
    float* out = (float*)d_out;

    zero_kernel<<<(NC * D + 255) / 256, 256>>>();
    rownorm_kernel<<<N, 128>>>(img, txt, labels);
    gemm_neg_kernel<<<N / ROWS_B, 256>>>();
    finish_kernel<<<N / 256, 256>>>(out);
}